// round 4
// baseline (speedup 1.0000x reference)
#include <cuda_runtime.h>
#include <cuda_fp16.h>
#include <cstdint>

// ============================================================================
// Problem constants
// ============================================================================
#define NTOK   8192
#define DIM    2048
#define NELEM  (NTOK*DIM)       // 16,777,216
#define WELEM  (DIM*DIM)        // 4,194,304

// ============================================================================
// Device-global scratch (allocation-free per harness rules)
// ============================================================================
__device__ __half g_xh [NELEM];
__device__ __half g_h1 [NELEM];
__device__ __half g_h2 [NELEM];
__device__ __half g_h3 [NELEM];
__device__ __half g_w1h[WELEM];
__device__ __half g_w3h[WELEM];
__device__ __half g_w2h[WELEM];
__device__ int    g_ri [NTOK*2];
__device__ float  g_rg [NTOK*2];

// ============================================================================
// Helpers (all plain sm_80/sm_90 features -- nothing "a"-gated)
// ============================================================================
__device__ __forceinline__ uint32_t smem_u32(const void* p) {
    uint32_t a;
    asm("{ .reg .u64 t; cvta.to.shared.u64 t, %1; cvt.u32.u64 %0, t; }"
        : "=r"(a) : "l"(p));
    return a;
}
#define CPA16(dst, src) \
    asm volatile("cp.async.cg.shared.global [%0], [%1], 16;" :: "r"(dst), "l"(src))
#define CPA_COMMIT() asm volatile("cp.async.commit_group;" ::: "memory")
#define CPA_WAIT2()  asm volatile("cp.async.wait_group 2;" ::: "memory")

#define LDSM_X4(r0, r1, r2, r3, addr) \
    asm volatile("ldmatrix.sync.aligned.m8n8.x4.shared.b16 {%0,%1,%2,%3}, [%4];" \
                 : "=r"(r0), "=r"(r1), "=r"(r2), "=r"(r3) : "r"(addr))

__device__ __forceinline__ void mma16816(float* d, const uint32_t* a, const uint32_t* b) {
    asm volatile(
        "mma.sync.aligned.m16n8k16.row.col.f32.f16.f16.f32 "
        "{%0,%1,%2,%3}, {%4,%5,%6,%7}, {%8,%9}, {%0,%1,%2,%3};"
        : "+f"(d[0]), "+f"(d[1]), "+f"(d[2]), "+f"(d[3])
        : "r"(a[0]), "r"(a[1]), "r"(a[2]), "r"(a[3]), "r"(b[0]), "r"(b[1]));
}

// ============================================================================
// GEMM: C[M,N] = A[M,K] @ B[N,K]^T   (fp16 in, fp32 accum, fp16 out, opt SiLU)
// M=8192, N=2048, K=2048. Tile 128x128, BK=32 halves, 4-stage cp.async.
// 8 warps in 2(M) x 4(N); warp tile 64x32.
// SMEM tile layout: [128 rows][32 halves] = 64B/row, 4x16B chunks,
// chunk swizzle: c ^= (row & 3)  -> conflict-free ldmatrix + cp.async.
// ============================================================================
#define BM 128
#define BN 128
#define BK 32                  // halves per K-chunk
#define STAGES 4
#define KTOT 2048
#define NIT (KTOT / BK)        // 64
#define TILE_B (BM * BK * 2)   // 8192 bytes per operand tile
#define STAGE_B (2 * TILE_B)   // 16384 (A then B)
#define SMEM_TOTAL (STAGES * STAGE_B)   // 65536

__device__ __forceinline__ uint32_t sw_addr(uint32_t base, int row, int chunk) {
    return base + row * 64 + ((chunk ^ (row & 3)) << 4);
}

__global__ void __launch_bounds__(256, 2)
gemm_f16(const __half* __restrict__ A, const __half* __restrict__ Bw,
         __half* __restrict__ C, int do_silu)
{
    extern __shared__ __align__(128) char smem[];
    const uint32_t sb = smem_u32(smem);
    const int tid = threadIdx.x, wid = tid >> 5, lane = tid & 31;
    const int wm = wid & 1, wn = wid >> 1;        // warp grid 2 x 4
    const int m0 = blockIdx.y * BM;
    const int n0 = blockIdx.x * BN;
    const __half* Ab = A  + (size_t)m0 * KTOT;
    const __half* Bb = Bw + (size_t)n0 * KTOT;

    // cp.async thread mapping: 512 16B-chunks per operand tile, 2 per thread
    const int ld_row = tid >> 1;                  // 0..127
    const int ld_c0  = (tid & 1) * 2;             // 0 or 2

    // ldmatrix lane mapping
    const int r   = lane & 7;
    const int sel = lane >> 3;
    // A: row = wm*64 + mt*16 + (sel&1)*8 + r ; chunk = ks*2 + (sel>>1)
    const int a_row_base = wm * 64 + (sel & 1) * 8 + r;
    const int a_chunk_sel = sel >> 1;
    // B: row(n) = wn*32 + ntp*16 + (sel>>1)*8 + r ; chunk = ks*2 + (sel&1)
    const int b_row_base = wn * 32 + (sel >> 1) * 8 + r;
    const int b_chunk_sel = sel & 1;

    float acc[4][4][4];
    #pragma unroll
    for (int mt = 0; mt < 4; mt++)
        #pragma unroll
        for (int nt = 0; nt < 4; nt++)
            #pragma unroll
            for (int i = 0; i < 4; i++) acc[mt][nt][i] = 0.f;

    // ---- prologue: fill STAGES-1 stages
    #pragma unroll
    for (int s = 0; s < STAGES - 1; s++) {
        const int kg = s * BK;
        const uint32_t sA = sb + s * STAGE_B;
        const uint32_t sB = sA + TILE_B;
        #pragma unroll
        for (int c = 0; c < 2; c++) {
            CPA16(sw_addr(sA, ld_row, ld_c0 + c), Ab + (size_t)ld_row * KTOT + kg + (ld_c0 + c) * 8);
            CPA16(sw_addr(sB, ld_row, ld_c0 + c), Bb + (size_t)ld_row * KTOT + kg + (ld_c0 + c) * 8);
        }
        CPA_COMMIT();
    }

    int fetch = STAGES - 1;
    for (int it = 0; it < NIT; ++it) {
        CPA_WAIT2();
        __syncthreads();
        // issue next stage (or dummy commit to keep wait_group semantics sound)
        if (fetch < NIT) {
            const int s = fetch & (STAGES - 1);
            const int kg = fetch * BK;
            const uint32_t sA = sb + s * STAGE_B;
            const uint32_t sB = sA + TILE_B;
            #pragma unroll
            for (int c = 0; c < 2; c++) {
                CPA16(sw_addr(sA, ld_row, ld_c0 + c), Ab + (size_t)ld_row * KTOT + kg + (ld_c0 + c) * 8);
                CPA16(sw_addr(sB, ld_row, ld_c0 + c), Bb + (size_t)ld_row * KTOT + kg + (ld_c0 + c) * 8);
            }
            fetch++;
        }
        CPA_COMMIT();

        // ---- compute current stage
        const int s = it & (STAGES - 1);
        const uint32_t sA = sb + s * STAGE_B;
        const uint32_t sB = sA + TILE_B;
        #pragma unroll
        for (int ks = 0; ks < 2; ks++) {
            uint32_t a[4][4];
            #pragma unroll
            for (int mt = 0; mt < 4; mt++)
                LDSM_X4(a[mt][0], a[mt][1], a[mt][2], a[mt][3],
                        sw_addr(sA, a_row_base + mt * 16, ks * 2 + a_chunk_sel));
            uint32_t b[4][2];
            #pragma unroll
            for (int ntp = 0; ntp < 2; ntp++) {
                uint32_t b0, b1, b2, b3;
                LDSM_X4(b0, b1, b2, b3,
                        sw_addr(sB, b_row_base + ntp * 16, ks * 2 + b_chunk_sel));
                b[2 * ntp][0] = b0; b[2 * ntp][1] = b1;
                b[2 * ntp + 1][0] = b2; b[2 * ntp + 1][1] = b3;
            }
            #pragma unroll
            for (int mt = 0; mt < 4; mt++)
                #pragma unroll
                for (int nt = 0; nt < 4; nt++)
                    mma16816(acc[mt][nt], a[mt], b[nt]);
        }
    }
    // drain remaining async groups before smem is reused/exit
    asm volatile("cp.async.wait_group 0;" ::: "memory");

    // ---- epilogue: fp32 accum -> (SiLU) -> fp16 store
    const int erow = m0 + wm * 64 + (lane >> 2);
    const int ecol = n0 + wn * 32 + 2 * (lane & 3);
    #pragma unroll
    for (int mt = 0; mt < 4; mt++) {
        #pragma unroll
        for (int nt = 0; nt < 4; nt++) {
            float v0 = acc[mt][nt][0], v1 = acc[mt][nt][1];
            float v2 = acc[mt][nt][2], v3 = acc[mt][nt][3];
            if (do_silu) {
                v0 = v0 * __frcp_rn(1.0f + __expf(-v0));
                v1 = v1 * __frcp_rn(1.0f + __expf(-v1));
                v2 = v2 * __frcp_rn(1.0f + __expf(-v2));
                v3 = v3 * __frcp_rn(1.0f + __expf(-v3));
            }
            __half2 h01 = __floats2half2_rn(v0, v1);
            __half2 h23 = __floats2half2_rn(v2, v3);
            const int row = erow + mt * 16;
            const int col = ecol + nt * 8;
            *reinterpret_cast<__half2*>(C + (size_t)row * DIM + col) = h01;
            *reinterpret_cast<__half2*>(C + (size_t)(row + 8) * DIM + col) = h23;
        }
    }
}

// ============================================================================
// fp32 -> fp16 convert (vectorized)
// ============================================================================
__global__ void f2h_kernel(const float4* __restrict__ in, uint2* __restrict__ out, int n4) {
    int i = blockIdx.x * blockDim.x + threadIdx.x;
    if (i < n4) {
        float4 v = in[i];
        __half2 a = __floats2half2_rn(v.x, v.y);
        __half2 b = __floats2half2_rn(v.z, v.w);
        out[i] = make_uint2(*reinterpret_cast<uint32_t*>(&a),
                            *reinterpret_cast<uint32_t*>(&b));
    }
}

// ============================================================================
// Router: logits = x @ wr^T, top-2, gates.  One warp per token.
// top-k of softmax == top-k of logits (monotone); gate normalization cancels
// the softmax denominator: g0 = 1/(1+exp(l1-l0)).
// ============================================================================
__global__ void router_kernel(const float* __restrict__ x, const float* __restrict__ wr,
                              int* __restrict__ ri, float* __restrict__ rg) {
    int warp = (blockIdx.x * blockDim.x + threadIdx.x) >> 5;
    int lane = threadIdx.x & 31;
    if (warp >= NTOK) return;
    const float4* xr = reinterpret_cast<const float4*>(x + (size_t)warp * DIM);
    float acc[8] = {0.f, 0.f, 0.f, 0.f, 0.f, 0.f, 0.f, 0.f};
    for (int j = 0; j < 16; j++) {
        float4 xv = xr[j * 32 + lane];
        #pragma unroll
        for (int e = 0; e < 8; e++) {
            float4 wv = reinterpret_cast<const float4*>(wr + (size_t)e * DIM)[j * 32 + lane];
            acc[e] += xv.x * wv.x + xv.y * wv.y + xv.z * wv.z + xv.w * wv.w;
        }
    }
    #pragma unroll
    for (int e = 0; e < 8; e++)
        #pragma unroll
        for (int o = 16; o; o >>= 1) acc[e] += __shfl_xor_sync(0xFFFFFFFFu, acc[e], o);
    if (lane == 0) {
        float m0 = -1e30f, m1 = -1e30f; int i0 = 0, i1 = 0;
        #pragma unroll
        for (int e = 0; e < 8; e++) {
            float p = acc[e];
            if (p > m0)      { m1 = m0; i1 = i0; m0 = p; i0 = e; }
            else if (p > m1) { m1 = p; i1 = e; }
        }
        float g0 = 1.0f / (1.0f + expf(m1 - m0));
        ri[warp * 2]     = i0;
        ri[warp * 2 + 1] = i1;
        rg[warp * 2]     = g0;
        rg[warp * 2 + 1] = 1.0f - g0;
    }
}

// ============================================================================
// Zero the output buffer
// ============================================================================
__global__ void zero_kernel(float4* __restrict__ p, int n4) {
    int i = blockIdx.x * blockDim.x + threadIdx.x;
    if (i < n4) p[i] = make_float4(0.f, 0.f, 0.f, 0.f);
}

// ============================================================================
// Final reduce: out[e, d] += sum_n gate[n,e] * h3[n, d], e in 0..7
// (scatter indices are expert ids -> only rows 0..7 of out are nonzero)
// ============================================================================
__global__ void reduce_kernel(const __half* __restrict__ h3,
                              const int* __restrict__ ri, const float* __restrict__ rg,
                              float* __restrict__ out) {
    int d  = blockIdx.x * 256 + threadIdx.x;
    int nb = blockIdx.y;
    float acc[8] = {0.f, 0.f, 0.f, 0.f, 0.f, 0.f, 0.f, 0.f};
    for (int nn = 0; nn < 128; nn++) {
        int n = nb * 128 + nn;
        float h = __half2float(h3[(size_t)n * DIM + d]);
        int   i0 = ri[n * 2], i1 = ri[n * 2 + 1];
        float g0 = rg[n * 2], g1 = rg[n * 2 + 1];
        #pragma unroll
        for (int e = 0; e < 8; e++) {
            float g = (i0 == e ? g0 : 0.f) + (i1 == e ? g1 : 0.f);
            acc[e] = fmaf(g, h, acc[e]);
        }
    }
    #pragma unroll
    for (int e = 0; e < 8; e++)
        atomicAdd(&out[(size_t)e * DIM + d], acc[e]);
}

// ============================================================================
// kernel_launch
// ============================================================================
extern "C" void kernel_launch(void* const* d_in, const int* in_sizes, int n_in,
                              void* d_out, int out_size) {
    const float* x  = (const float*)d_in[0];
    const float* w1 = (const float*)d_in[1];
    const float* w3 = (const float*)d_in[2];
    const float* w2 = (const float*)d_in[3];
    const float* wr = (const float*)d_in[4];
    float* out = (float*)d_out;

    void *p_xh, *p_h1, *p_h2, *p_h3, *p_w1, *p_w3, *p_w2, *p_ri, *p_rg;
    cudaGetSymbolAddress(&p_xh, g_xh);
    cudaGetSymbolAddress(&p_h1, g_h1);
    cudaGetSymbolAddress(&p_h2, g_h2);
    cudaGetSymbolAddress(&p_h3, g_h3);
    cudaGetSymbolAddress(&p_w1, g_w1h);
    cudaGetSymbolAddress(&p_w3, g_w3h);
    cudaGetSymbolAddress(&p_w2, g_w2h);
    cudaGetSymbolAddress(&p_ri, g_ri);
    cudaGetSymbolAddress(&p_rg, g_rg);

    cudaFuncSetAttribute(gemm_f16, cudaFuncAttributeMaxDynamicSharedMemorySize, SMEM_TOTAL);

    // 1) converts
    {
        int n4 = NELEM / 4;
        f2h_kernel<<<(n4 + 255) / 256, 256>>>((const float4*)x, (uint2*)p_xh, n4);
        int w4 = WELEM / 4;
        f2h_kernel<<<(w4 + 255) / 256, 256>>>((const float4*)w1, (uint2*)p_w1, w4);
        f2h_kernel<<<(w4 + 255) / 256, 256>>>((const float4*)w3, (uint2*)p_w3, w4);
        f2h_kernel<<<(w4 + 255) / 256, 256>>>((const float4*)w2, (uint2*)p_w2, w4);
    }
    // 2) router
    router_kernel<<<NTOK / 8, 256>>>(x, wr, (int*)p_ri, (float*)p_rg);
    // 3) zero output
    zero_kernel<<<(out_size / 4 + 255) / 256, 256>>>((float4*)out, out_size / 4);
    // 4) three GEMMs
    dim3 grid(DIM / BN, NTOK / BM);  // (16, 64)
    gemm_f16<<<grid, 256, SMEM_TOTAL>>>((const __half*)p_xh, (const __half*)p_w1, (__half*)p_h1, 1);
    gemm_f16<<<grid, 256, SMEM_TOTAL>>>((const __half*)p_h1, (const __half*)p_w3, (__half*)p_h2, 1);
    gemm_f16<<<grid, 256, SMEM_TOTAL>>>((const __half*)p_h2, (const __half*)p_w2, (__half*)p_h3, 0);
    // 5) expert-row reduce
    reduce_kernel<<<dim3(DIM / 256, NTOK / 128), 256>>>((const __half*)p_h3,
                                                        (const int*)p_ri, (const float*)p_rg, out);
}

// round 6
// speedup vs baseline: 1.1184x; 1.1184x over previous
#include <cuda_runtime.h>
#include <cuda_fp16.h>
#include <cstdint>

// ============================================================================
// Problem constants
// ============================================================================
#define NTOK   8192
#define DIM    2048
#define NELEM  (NTOK*DIM)       // 16,777,216
#define WELEM  (DIM*DIM)        // 4,194,304

// ============================================================================
// Device-global scratch (allocation-free per harness rules)
// ============================================================================
__device__ __half g_xh [NELEM];
__device__ __half g_h1 [NELEM];
__device__ __half g_h2 [NELEM];
__device__ __half g_h3 [NELEM];
__device__ __half g_w1h[WELEM];
__device__ __half g_w3h[WELEM];
__device__ __half g_w2h[WELEM];
__device__ int    g_ri [NTOK*2];
__device__ float  g_rg [NTOK*2];

// ============================================================================
// Helpers (all plain sm_80/sm_90 features -- nothing "a"-gated)
// ============================================================================
__device__ __forceinline__ uint32_t smem_u32(const void* p) {
    uint32_t a;
    asm("{ .reg .u64 t; cvta.to.shared.u64 t, %1; cvt.u32.u64 %0, t; }"
        : "=r"(a) : "l"(p));
    return a;
}
#define CPA16(dst, src) \
    asm volatile("cp.async.cg.shared.global [%0], [%1], 16;" :: "r"(dst), "l"(src))
#define CPA_COMMIT() asm volatile("cp.async.commit_group;" ::: "memory")
#define CPA_WAIT1()  asm volatile("cp.async.wait_group 1;" ::: "memory")

#define LDSM_X4(r0, r1, r2, r3, addr) \
    asm volatile("ldmatrix.sync.aligned.m8n8.x4.shared.b16 {%0,%1,%2,%3}, [%4];" \
                 : "=r"(r0), "=r"(r1), "=r"(r2), "=r"(r3) : "r"(addr))

__device__ __forceinline__ void mma16816(float* d, const uint32_t* a, const uint32_t* b) {
    asm volatile(
        "mma.sync.aligned.m16n8k16.row.col.f32.f16.f16.f32 "
        "{%0,%1,%2,%3}, {%4,%5,%6,%7}, {%8,%9}, {%0,%1,%2,%3};"
        : "+f"(d[0]), "+f"(d[1]), "+f"(d[2]), "+f"(d[3])
        : "r"(a[0]), "r"(a[1]), "r"(a[2]), "r"(a[3]), "r"(b[0]), "r"(b[1]));
}

// ============================================================================
// GEMM: C[M,N] = A[M,K] @ B[N,K]^T   (fp16 in, fp32 accum, fp16 out, opt SiLU)
// M=8192, N=2048, K=2048. Tile 128x128, BK=64 halves (= 128B rows), 3 stages.
// 8 warps in 2(M) x 4(N); warp tile 64x32.
// SMEM tile: [128 rows][64 halves] = 128B/row, 8x16B chunks per row,
// chunk swizzle: c ^= (row & 7)  -> ALL 8 bank bits covered: conflict-free
// ldmatrix phases (8 consecutive rows -> 8 distinct 16B banks) and cp.async.
// ============================================================================
#define BM 128
#define BN 128
#define BK 64                  // halves per K-chunk (128 bytes per row)
#define STAGES 3
#define KTOT 2048
#define NIT (KTOT / BK)        // 32
#define TILE_B (BM * BK * 2)   // 16384 bytes per operand tile
#define STAGE_B (2 * TILE_B)   // 32768 (A then B)
#define SMEM_TOTAL (STAGES * STAGE_B)   // 98304

__device__ __forceinline__ uint32_t sw_addr(uint32_t base, int row, int chunk) {
    return base + row * 128 + ((chunk ^ (row & 7)) << 4);
}

__global__ void __launch_bounds__(256, 2)
gemm_f16(const __half* __restrict__ A, const __half* __restrict__ Bw,
         __half* __restrict__ C, int do_silu)
{
    extern __shared__ __align__(128) char smem[];
    const uint32_t sb = smem_u32(smem);
    const int tid = threadIdx.x, wid = tid >> 5, lane = tid & 31;
    const int wm = wid & 1, wn = wid >> 1;        // warp grid 2 x 4
    const int m0 = blockIdx.y * BM;
    const int n0 = blockIdx.x * BN;
    const __half* Ab = A  + (size_t)m0 * KTOT;
    const __half* Bb = Bw + (size_t)n0 * KTOT;

    // cp.async mapping: 1024 16B-chunks per operand tile, 4 per thread
    const int ld_row = tid >> 1;                  // 0..127
    const int ld_c0  = (tid & 1) * 4;             // 0 or 4

    // ldmatrix lane mapping
    const int r   = lane & 7;
    const int sel = lane >> 3;
    const int a_row_base  = wm * 64 + (sel & 1) * 8 + r;
    const int a_chunk_sel = sel >> 1;
    const int b_row_base  = wn * 32 + (sel >> 1) * 8 + r;
    const int b_chunk_sel = sel & 1;

    float acc[4][4][4];
    #pragma unroll
    for (int mt = 0; mt < 4; mt++)
        #pragma unroll
        for (int nt = 0; nt < 4; nt++)
            #pragma unroll
            for (int i = 0; i < 4; i++) acc[mt][nt][i] = 0.f;

    // ---- prologue: fill STAGES-1 = 2 stages
    #pragma unroll
    for (int s = 0; s < STAGES - 1; s++) {
        const int kg = s * BK;
        const uint32_t sA = sb + s * STAGE_B;
        const uint32_t sB = sA + TILE_B;
        #pragma unroll
        for (int c = 0; c < 4; c++) {
            CPA16(sw_addr(sA, ld_row, ld_c0 + c), Ab + (size_t)ld_row * KTOT + kg + (ld_c0 + c) * 8);
            CPA16(sw_addr(sB, ld_row, ld_c0 + c), Bb + (size_t)ld_row * KTOT + kg + (ld_c0 + c) * 8);
        }
        CPA_COMMIT();
    }

    int fetch = STAGES - 1;
    int slot_c = 0;                                // compute slot (mod 3)
    int slot_f = STAGES - 1;                       // fetch slot (mod 3)
    for (int it = 0; it < NIT; ++it) {
        CPA_WAIT1();
        __syncthreads();
        // issue next stage (empty commit keeps wait_group numbering sound)
        if (fetch < NIT) {
            const int kg = fetch * BK;
            const uint32_t sA = sb + slot_f * STAGE_B;
            const uint32_t sB = sA + TILE_B;
            #pragma unroll
            for (int c = 0; c < 4; c++) {
                CPA16(sw_addr(sA, ld_row, ld_c0 + c), Ab + (size_t)ld_row * KTOT + kg + (ld_c0 + c) * 8);
                CPA16(sw_addr(sB, ld_row, ld_c0 + c), Bb + (size_t)ld_row * KTOT + kg + (ld_c0 + c) * 8);
            }
            fetch++;
            if (++slot_f == STAGES) slot_f = 0;
        }
        CPA_COMMIT();

        // ---- compute current stage: 4 k16 steps
        const uint32_t sA = sb + slot_c * STAGE_B;
        const uint32_t sB = sA + TILE_B;
        if (++slot_c == STAGES) slot_c = 0;
        #pragma unroll
        for (int ks = 0; ks < 4; ks++) {
            uint32_t a[4][4];
            #pragma unroll
            for (int mt = 0; mt < 4; mt++)
                LDSM_X4(a[mt][0], a[mt][1], a[mt][2], a[mt][3],
                        sw_addr(sA, a_row_base + mt * 16, ks * 2 + a_chunk_sel));
            uint32_t b[4][2];
            #pragma unroll
            for (int ntp = 0; ntp < 2; ntp++) {
                uint32_t b0, b1, b2, b3;
                LDSM_X4(b0, b1, b2, b3,
                        sw_addr(sB, b_row_base + ntp * 16, ks * 2 + b_chunk_sel));
                b[2 * ntp][0] = b0; b[2 * ntp][1] = b1;
                b[2 * ntp + 1][0] = b2; b[2 * ntp + 1][1] = b3;
            }
            #pragma unroll
            for (int mt = 0; mt < 4; mt++)
                #pragma unroll
                for (int nt = 0; nt < 4; nt++)
                    mma16816(acc[mt][nt], a[mt], b[nt]);
        }
    }
    asm volatile("cp.async.wait_group 0;" ::: "memory");

    // ---- epilogue: fp32 accum -> (SiLU) -> fp16 store
    const int erow = m0 + wm * 64 + (lane >> 2);
    const int ecol = n0 + wn * 32 + 2 * (lane & 3);
    #pragma unroll
    for (int mt = 0; mt < 4; mt++) {
        #pragma unroll
        for (int nt = 0; nt < 4; nt++) {
            float v0 = acc[mt][nt][0], v1 = acc[mt][nt][1];
            float v2 = acc[mt][nt][2], v3 = acc[mt][nt][3];
            if (do_silu) {
                v0 = v0 * __frcp_rn(1.0f + __expf(-v0));
                v1 = v1 * __frcp_rn(1.0f + __expf(-v1));
                v2 = v2 * __frcp_rn(1.0f + __expf(-v2));
                v3 = v3 * __frcp_rn(1.0f + __expf(-v3));
            }
            __half2 h01 = __floats2half2_rn(v0, v1);
            __half2 h23 = __floats2half2_rn(v2, v3);
            const int row = erow + mt * 16;
            const int col = ecol + nt * 8;
            *reinterpret_cast<__half2*>(C + (size_t)row * DIM + col) = h01;
            *reinterpret_cast<__half2*>(C + (size_t)(row + 8) * DIM + col) = h23;
        }
    }
}

// ============================================================================
// fp32 -> fp16 convert (vectorized)
// ============================================================================
__global__ void f2h_kernel(const float4* __restrict__ in, uint2* __restrict__ out, int n4) {
    int i = blockIdx.x * blockDim.x + threadIdx.x;
    if (i < n4) {
        float4 v = in[i];
        __half2 a = __floats2half2_rn(v.x, v.y);
        __half2 b = __floats2half2_rn(v.z, v.w);
        out[i] = make_uint2(*reinterpret_cast<uint32_t*>(&a),
                            *reinterpret_cast<uint32_t*>(&b));
    }
}

// ============================================================================
// Router: logits = x @ wr^T, top-2, gates.  One warp per token.
// top-k of softmax == top-k of logits (monotone); gate normalization cancels
// the softmax denominator: g0 = 1/(1+exp(l1-l0)).
// ============================================================================
__global__ void router_kernel(const float* __restrict__ x, const float* __restrict__ wr,
                              int* __restrict__ ri, float* __restrict__ rg) {
    int warp = (blockIdx.x * blockDim.x + threadIdx.x) >> 5;
    int lane = threadIdx.x & 31;
    if (warp >= NTOK) return;
    const float4* xr = reinterpret_cast<const float4*>(x + (size_t)warp * DIM);
    float acc[8] = {0.f, 0.f, 0.f, 0.f, 0.f, 0.f, 0.f, 0.f};
    for (int j = 0; j < 16; j++) {
        float4 xv = xr[j * 32 + lane];
        #pragma unroll
        for (int e = 0; e < 8; e++) {
            float4 wv = reinterpret_cast<const float4*>(wr + (size_t)e * DIM)[j * 32 + lane];
            acc[e] += xv.x * wv.x + xv.y * wv.y + xv.z * wv.z + xv.w * wv.w;
        }
    }
    #pragma unroll
    for (int e = 0; e < 8; e++)
        #pragma unroll
        for (int o = 16; o; o >>= 1) acc[e] += __shfl_xor_sync(0xFFFFFFFFu, acc[e], o);
    if (lane == 0) {
        float m0 = -1e30f, m1 = -1e30f; int i0 = 0, i1 = 0;
        #pragma unroll
        for (int e = 0; e < 8; e++) {
            float p = acc[e];
            if (p > m0)      { m1 = m0; i1 = i0; m0 = p; i0 = e; }
            else if (p > m1) { m1 = p; i1 = e; }
        }
        float g0 = 1.0f / (1.0f + expf(m1 - m0));
        ri[warp * 2]     = i0;
        ri[warp * 2 + 1] = i1;
        rg[warp * 2]     = g0;
        rg[warp * 2 + 1] = 1.0f - g0;
    }
}

// ============================================================================
// Zero the output buffer
// ============================================================================
__global__ void zero_kernel(float4* __restrict__ p, int n4) {
    int i = blockIdx.x * blockDim.x + threadIdx.x;
    if (i < n4) p[i] = make_float4(0.f, 0.f, 0.f, 0.f);
}

// ============================================================================
// Final reduce: out[e, d] += sum_n gate[n,e] * h3[n, d], e in 0..7
// (scatter indices are expert ids -> only rows 0..7 of out are nonzero)
// ============================================================================
__global__ void reduce_kernel(const __half* __restrict__ h3,
                              const int* __restrict__ ri, const float* __restrict__ rg,
                              float* __restrict__ out) {
    int d  = blockIdx.x * 256 + threadIdx.x;
    int nb = blockIdx.y;
    float acc[8] = {0.f, 0.f, 0.f, 0.f, 0.f, 0.f, 0.f, 0.f};
    for (int nn = 0; nn < 128; nn++) {
        int n = nb * 128 + nn;
        float h = __half2float(h3[(size_t)n * DIM + d]);
        int   i0 = ri[n * 2], i1 = ri[n * 2 + 1];
        float g0 = rg[n * 2], g1 = rg[n * 2 + 1];
        #pragma unroll
        for (int e = 0; e < 8; e++) {
            float g = (i0 == e ? g0 : 0.f) + (i1 == e ? g1 : 0.f);
            acc[e] = fmaf(g, h, acc[e]);
        }
    }
    #pragma unroll
    for (int e = 0; e < 8; e++)
        atomicAdd(&out[(size_t)e * DIM + d], acc[e]);
}

// ============================================================================
// kernel_launch
// (GEMM1 is launch #6 so ncu -s 5 -c 1 captures it; zero moved after GEMMs,
//  still stream-ordered before reduce.)
// ============================================================================
extern "C" void kernel_launch(void* const* d_in, const int* in_sizes, int n_in,
                              void* d_out, int out_size) {
    const float* x  = (const float*)d_in[0];
    const float* w1 = (const float*)d_in[1];
    const float* w3 = (const float*)d_in[2];
    const float* w2 = (const float*)d_in[3];
    const float* wr = (const float*)d_in[4];
    float* out = (float*)d_out;

    void *p_xh, *p_h1, *p_h2, *p_h3, *p_w1, *p_w3, *p_w2, *p_ri, *p_rg;
    cudaGetSymbolAddress(&p_xh, g_xh);
    cudaGetSymbolAddress(&p_h1, g_h1);
    cudaGetSymbolAddress(&p_h2, g_h2);
    cudaGetSymbolAddress(&p_h3, g_h3);
    cudaGetSymbolAddress(&p_w1, g_w1h);
    cudaGetSymbolAddress(&p_w3, g_w3h);
    cudaGetSymbolAddress(&p_w2, g_w2h);
    cudaGetSymbolAddress(&p_ri, g_ri);
    cudaGetSymbolAddress(&p_rg, g_rg);

    cudaFuncSetAttribute(gemm_f16, cudaFuncAttributeMaxDynamicSharedMemorySize, SMEM_TOTAL);

    // 1) converts (launches 1-4)
    {
        int n4 = NELEM / 4;
        f2h_kernel<<<(n4 + 255) / 256, 256>>>((const float4*)x, (uint2*)p_xh, n4);
        int w4 = WELEM / 4;
        f2h_kernel<<<(w4 + 255) / 256, 256>>>((const float4*)w1, (uint2*)p_w1, w4);
        f2h_kernel<<<(w4 + 255) / 256, 256>>>((const float4*)w3, (uint2*)p_w3, w4);
        f2h_kernel<<<(w4 + 255) / 256, 256>>>((const float4*)w2, (uint2*)p_w2, w4);
    }
    // 2) router (launch 5)
    router_kernel<<<NTOK / 8, 256>>>(x, wr, (int*)p_ri, (float*)p_rg);
    // 3) three GEMMs (launches 6-8)
    dim3 grid(DIM / BN, NTOK / BM);  // (16, 64)
    gemm_f16<<<grid, 256, SMEM_TOTAL>>>((const __half*)p_xh, (const __half*)p_w1, (__half*)p_h1, 1);
    gemm_f16<<<grid, 256, SMEM_TOTAL>>>((const __half*)p_h1, (const __half*)p_w3, (__half*)p_h2, 1);
    gemm_f16<<<grid, 256, SMEM_TOTAL>>>((const __half*)p_h2, (const __half*)p_w2, (__half*)p_h3, 0);
    // 4) zero output, then expert-row reduce
    zero_kernel<<<(out_size / 4 + 255) / 256, 256>>>((float4*)out, out_size / 4);
    reduce_kernel<<<dim3(DIM / 256, NTOK / 128), 256>>>((const __half*)p_h3,
                                                        (const int*)p_ri, (const float*)p_rg, out);
}